// round 1
// baseline (speedup 1.0000x reference)
#include <cuda_runtime.h>

// Fused kernel: per batch b,
//   phase 1: h[t,0:256] = W1 @ x[b,t,:]   (f32x2 packed FMA, weights in regs)
//   phase 2: 96 stateful material chains update h tile in place -> ys
//   phase 3: out[b,t,0:16] = softplus(W2) @ ys[t,:]  (f32x2 packed FMA)
// One CTA per batch (grid=256), 128 threads, T processed in tiles of 64.

typedef unsigned long long u64;

#define NTHREADS 128
#define TT 64
#define NTILES 16
#define BPAD 257
#define LS 256

__device__ __forceinline__ u64 ffma2(u64 a, u64 b, u64 c) {
    u64 d;
    asm("fma.rn.f32x2 %0, %1, %2, %3;" : "=l"(d) : "l"(a), "l"(b), "l"(c));
    return d;
}
__device__ __forceinline__ u64 pack2(float a, float b) {
    u64 r; asm("mov.b64 %0, {%1, %2};" : "=l"(r) : "f"(a), "f"(b)); return r;
}
__device__ __forceinline__ u64 dup2(float a) {
    u64 r; asm("mov.b64 %0, {%1, %1};" : "=l"(r) : "f"(a)); return r;
}
__device__ __forceinline__ float2 unpack2(u64 v) {
    float2 r; asm("mov.b64 {%0, %1}, %2;" : "=f"(r.x), "=f"(r.y) : "l"(v)); return r;
}

__global__ void __launch_bounds__(NTHREADS, 2)
fused_fea_kernel(const float* __restrict__ x, const float* __restrict__ W1,
                 const float* __restrict__ W2, float* __restrict__ out)
{
    extern __shared__ float sm[];
    float* W1s  = sm;                  // 4096 floats, [l][f]
    float* SW2s = sm + 4096;           // 4096 floats, transposed [l][o]
    float* xsd  = sm + 8192;           // 2048 floats, x tile duplicated (each value twice)
    float* buf  = sm + 8192 + 2048;    // TT * BPAD floats, h tile -> ys tile in place

    const int tid = threadIdx.x;
    const int b   = blockIdx.x;

    // Stage weights.
    for (int i = tid; i < 4096; i += NTHREADS) W1s[i] = W1[i];
    for (int i = tid; i < 4096; i += NTHREADS) {
        int o = i >> 8, l = i & 255;
        SW2s[l * 16 + o] = log1pf(expf(W2[i]));   // softplus, transposed for fc2
    }
    __syncthreads();

    // W1 rows for this thread's two output lanes (l = tid, tid+128), packed f32x2.
    u64 w1r[16];
#pragma unroll
    for (int f = 0; f < 16; ++f)
        w1r[f] = pack2(W1s[tid * 16 + f], W1s[(tid + 128) * 16 + f]);

    // Material constants (match reference float32 values).
    const float NUv    = 0.3f;
    const float CEL00  = 200.0f / 0.91f;          // E/(1-nu^2)
    const float CEL01  = CEL00 * 0.3f;
    const float CEL22  = CEL00 * 0.35f;           // * (1-nu)/2
    const float INV_E  = 1.0f / 200.0f;
    const float INV_G  = 2.6f / 200.0f;           // 2(1+nu)/E = 1/G
    const float GMOD   = 200.0f / 2.6f;
    const float SY0    = 2.0f, HARD = 10.0f;
    const float INV3GH = 1.0f / (3.0f * GMOD + HARD);
    const float KPEN   = 50.0f;
    const float D0     = 0.1f, DFm = 0.9f;        // deltaf - delta0

    // Per-thread state (threads 0..63 bulk points, 64..95 cohesive points).
    float ep1 = 0.f, ep2 = 0.f, ep12 = 0.f, epbar = 0.f, hist = 0.f;

    const float* xb = x   + (size_t)b * (1024 * 16);
    float*       ob = out + (size_t)b * (1024 * 16);

    for (int tile = 0; tile < NTILES; ++tile) {
        const int t0 = tile * TT;

        // Stage x tile, duplicated so phase-1 can LDS.64 straight into f32x2 FMA.
        for (int i = tid; i < TT * 16; i += NTHREADS) {
            float v = xb[t0 * 16 + i];
            xsd[2 * i] = v; xsd[2 * i + 1] = v;
        }
        __syncthreads();

        // ---- Phase 1: h tile = W1 @ x, 4 t-values in flight for ILP ----
#pragma unroll
        for (int tq = 0; tq < TT / 4; ++tq) {
            u64 a0 = 0ull, a1 = 0ull, a2 = 0ull, a3 = 0ull;
            const u64* xr = (const u64*)xsd + tq * 64;  // 4 timesteps * 16 features
#pragma unroll
            for (int f = 0; f < 16; ++f) {
                a0 = ffma2(w1r[f], xr[f],      a0);
                a1 = ffma2(w1r[f], xr[16 + f], a1);
                a2 = ffma2(w1r[f], xr[32 + f], a2);
                a3 = ffma2(w1r[f], xr[48 + f], a3);
            }
            float2 h0 = unpack2(a0), h1 = unpack2(a1), h2 = unpack2(a2), h3 = unpack2(a3);
            const int t = tq * 4;
            buf[(t + 0) * BPAD + tid] = h0.x;  buf[(t + 0) * BPAD + tid + 128] = h0.y;
            buf[(t + 1) * BPAD + tid] = h1.x;  buf[(t + 1) * BPAD + tid + 128] = h1.y;
            buf[(t + 2) * BPAD + tid] = h2.x;  buf[(t + 2) * BPAD + tid + 128] = h2.y;
            buf[(t + 3) * BPAD + tid] = h3.x;  buf[(t + 3) * BPAD + tid + 128] = h3.y;
        }
        __syncthreads();

        // ---- Phase 2: sequential material update (in place) ----
        if (tid < 64) {
            // J2 plane-stress radial return, one bulk point per thread.
            float* p = buf + tid * 3;
            for (int t = 0; t < TT; ++t, p += BPAD) {
                float e1 = p[0], e2 = p[1], e12 = p[2];
                float d1 = e1 - ep1, d2 = e2 - ep2, d12 = e12 - ep12;
                float s1  = CEL00 * d1 + CEL01 * d2;
                float s2  = CEL01 * d1 + CEL00 * d2;
                float s12 = CEL22 * d12;
                float q   = fmaxf(s1 * s1 - s1 * s2 + s2 * s2 + 3.0f * s12 * s12, 1e-12f);
                float seq = __fsqrt_rn(q);
                float fy  = seq - (SY0 + HARD * epbar);
                if (fy > 0.0f) {
                    float dep = fy * INV3GH;
                    epbar += dep;
                    float r = __fdiv_rn(SY0 + HARD * epbar, seq);
                    s1 *= r; s2 *= r; s12 *= r;
                    ep1  = e1  - (s1 - NUv * s2) * INV_E;
                    ep2  = e2  - (s2 - NUv * s1) * INV_E;
                    ep12 = e12 - s12 * INV_G;
                }
                p[0] = s1; p[1] = s2; p[2] = s12;
            }
        } else if (tid < 96) {
            // Turon cohesive bilinear damage, one point per thread.
            float* p = buf + 192 + (tid - 64) * 2;
            for (int t = 0; t < TT; ++t, p += BPAD) {
                float dn = p[0], ds = p[1];
                float dnp = fmaxf(dn, 0.0f);
                float lam = __fsqrt_rn(fmaxf(dnp * dnp + ds * ds, 1e-12f));
                hist = fmaxf(hist, lam);
                float dmg = __fdiv_rn(hist - D0, fmaxf(hist, 1e-12f) * DFm);
                dmg = fminf(fmaxf(dmg, 0.0f), 1.0f);
                float omd = 1.0f - dmg;
                p[0] = KPEN * dn * (dn > 0.0f ? omd : 1.0f);
                p[1] = omd * KPEN * ds;
            }
        }
        __syncthreads();

        // ---- Phase 3: out = SW2 @ ys. Thread owns 2 outputs (packed) x 4 timesteps ----
        {
            const int op = (tid & 7) * 2;     // output-channel pair
            const int tg = (tid >> 3) * 4;    // timestep group
            u64 a0 = 0ull, a1 = 0ull, a2 = 0ull, a3 = 0ull;
            const float* y0 = buf + tg * BPAD;
#pragma unroll 8
            for (int l = 0; l < LS; ++l) {
                u64 w = *(const u64*)(SW2s + l * 16 + op);
                a0 = ffma2(w, dup2(y0[l]),            a0);
                a1 = ffma2(w, dup2(y0[BPAD + l]),     a1);
                a2 = ffma2(w, dup2(y0[2 * BPAD + l]), a2);
                a3 = ffma2(w, dup2(y0[3 * BPAD + l]), a3);
            }
            float2 r0 = unpack2(a0), r1 = unpack2(a1), r2 = unpack2(a2), r3 = unpack2(a3);
            float* og = ob + (t0 + tg) * 16 + op;
            *(float2*)(og)      = r0;
            *(float2*)(og + 16) = r1;
            *(float2*)(og + 32) = r2;
            *(float2*)(og + 48) = r3;
        }
        __syncthreads();   // buf reused next tile
    }
}

extern "C" void kernel_launch(void* const* d_in, const int* in_sizes, int n_in,
                              void* d_out, int out_size)
{
    const float* x  = (const float*)d_in[0];
    const float* W1 = (const float*)d_in[1];
    const float* W2 = (const float*)d_in[2];
    float* out = (float*)d_out;

    const size_t smem = (size_t)(4096 + 4096 + 2048 + TT * BPAD) * sizeof(float); // 106752 B
    cudaFuncSetAttribute(fused_fea_kernel, cudaFuncAttributeMaxDynamicSharedMemorySize, (int)smem);
    fused_fea_kernel<<<256, NTHREADS, smem>>>(x, W1, W2, out);
}